// round 16
// baseline (speedup 1.0000x reference)
#include <cuda_runtime.h>
#include <cuda_bf16.h>
#include <cstddef>
#include <cstdint>

#define NMAX 50000
#define EMAX 600000
#define CCH 128
#define SLOTS 64
#define WP 40   // smem stride in bf16 (80B) - conflict-free fragment LDS

// ---------------- scratch (static device globals; no allocation) -------------
__device__ float g_y[(size_t)NMAX * CCH];
__device__ float g_h[(size_t)NMAX * CCH];
__device__ float g_agg[(size_t)NMAX * CCH];
__device__ int   g_cnt[NMAX];
__device__ int   g_slot[(size_t)NMAX * SLOTS];
__device__ int   g_src[(size_t)NMAX * SLOTS];
__device__ float g_sum[CCH];
__device__ float g_sumsq[CCH];

// ---------------- zero per-launch state ----------------
__global__ void k_zero(int n) {
    int i = blockIdx.x * blockDim.x + threadIdx.x;
    if (i < n) g_cnt[i] = 0;
    if (i < CCH) { g_sum[i] = 0.f; g_sumsq[i] = 0.f; }
}

// ---------------- bucket fill (slot = edge id, src prevalidated) -------------
__global__ void k_bucket(const int* __restrict__ ei, int nE, int n) {
    int e = blockIdx.x * blockDim.x + threadIdx.x;
    if (e < nE) {
        int t = ei[nE + e];                       // row 1 = target
        if ((unsigned)t < (unsigned)n) {
            int p = atomicAdd(&g_cnt[t], 1);
            if (p < SLOTS) {
                int s = ei[e];                    // row 0 = source
                if ((unsigned)s >= (unsigned)n) s = 0;
                g_slot[(size_t)t * SLOTS + p] = e;
                g_src [(size_t)t * SLOTS + p] = s;
            }
        }
    }
}

// ---------------- bf16 hi/lo split ----------------
__device__ __forceinline__ void split4(float4 v, uint2& h, uint2& l) {
    __nv_bfloat16 hx = __float2bfloat16(v.x);
    __nv_bfloat16 hy = __float2bfloat16(v.y);
    __nv_bfloat16 hz = __float2bfloat16(v.z);
    __nv_bfloat16 hw = __float2bfloat16(v.w);
    __nv_bfloat16 lx = __float2bfloat16(v.x - __bfloat162float(hx));
    __nv_bfloat16 ly = __float2bfloat16(v.y - __bfloat162float(hy));
    __nv_bfloat16 lz = __float2bfloat16(v.z - __bfloat162float(hz));
    __nv_bfloat16 lw = __float2bfloat16(v.w - __bfloat162float(hw));
    h.x = ((unsigned)__bfloat16_as_ushort(hy) << 16) | __bfloat16_as_ushort(hx);
    h.y = ((unsigned)__bfloat16_as_ushort(hw) << 16) | __bfloat16_as_ushort(hz);
    l.x = ((unsigned)__bfloat16_as_ushort(ly) << 16) | __bfloat16_as_ushort(lx);
    l.y = ((unsigned)__bfloat16_as_ushort(lw) << 16) | __bfloat16_as_ushort(lz);
}

// ---------------- GEMM via mma.sync bf16 (hi/lo split, fp32 accum) ----------
// one pass per launch: pass=0 -> y = x@Wg^T, pass=1 -> h = x@Wl^T.
__device__ __forceinline__ void mma_bf16(float* c, const unsigned* a, const unsigned* b) {
    asm volatile("mma.sync.aligned.m16n8k16.row.col.f32.bf16.bf16.f32 "
                 "{%0,%1,%2,%3}, {%4,%5,%6,%7}, {%8,%9}, {%0,%1,%2,%3};"
                 : "+f"(c[0]), "+f"(c[1]), "+f"(c[2]), "+f"(c[3])
                 : "r"(a[0]), "r"(a[1]), "r"(a[2]), "r"(a[3]),
                   "r"(b[0]), "r"(b[1]));
}

__global__ void __launch_bounds__(256, 2)
k_gemm(const float* __restrict__ x,
       const float* __restrict__ W,
       int n, int pass) {
    __shared__ __nv_bfloat16 Ah[128 * WP], Al[128 * WP];
    __shared__ __nv_bfloat16 Bh[128 * WP], Bl[128 * WP];
    int tid = threadIdx.x;
    int row0 = blockIdx.x * 128;
    float* outp = pass ? g_h : g_y;
    int wid = tid >> 5, lane = tid & 31;
    int gq = lane >> 2, qq = lane & 3;
    int warpM = (wid & 3) * 32, warpN = (wid >> 2) * 64;

    float acc[2][8][4];
    #pragma unroll
    for (int m = 0; m < 2; m++)
        #pragma unroll
        for (int j = 0; j < 8; j++)
            #pragma unroll
            for (int q = 0; q < 4; q++) acc[m][j][q] = 0.f;

    for (int p = 0; p < 4; p++) {
        int k0 = p * 32;
        __syncthreads();
        for (int i = tid; i < 1024; i += 256) {
            int r = i >> 3, q = i & 7;
            int rr = row0 + r; if (rr >= n) rr = n - 1;
            float4 xv = *(const float4*)(x + (size_t)rr * CCH + k0 + q * 4);
            uint2 h, l;
            split4(xv, h, l);
            *(uint2*)(Ah + r * WP + q * 4) = h;
            *(uint2*)(Al + r * WP + q * 4) = l;
            float4 wv = *(const float4*)(W + (size_t)r * CCH + k0 + q * 4);
            split4(wv, h, l);
            *(uint2*)(Bh + r * WP + q * 4) = h;
            *(uint2*)(Bl + r * WP + q * 4) = l;
        }
        __syncthreads();

        #pragma unroll
        for (int ks = 0; ks < 2; ks++) {
            int kb = ks * 16;
            unsigned ah[2][4], al[2][4];
            #pragma unroll
            for (int m = 0; m < 2; m++) {
                int rb = warpM + m * 16 + gq;
                int o0 = rb * WP + kb + qq * 2;
                int o1 = (rb + 8) * WP + kb + qq * 2;
                ah[m][0] = *(const unsigned*)(Ah + o0);
                ah[m][1] = *(const unsigned*)(Ah + o1);
                ah[m][2] = *(const unsigned*)(Ah + o0 + 8);
                ah[m][3] = *(const unsigned*)(Ah + o1 + 8);
                al[m][0] = *(const unsigned*)(Al + o0);
                al[m][1] = *(const unsigned*)(Al + o1);
                al[m][2] = *(const unsigned*)(Al + o0 + 8);
                al[m][3] = *(const unsigned*)(Al + o1 + 8);
            }
            #pragma unroll
            for (int j = 0; j < 8; j++) {
                int cbp = (warpN + j * 8 + gq) * WP + kb + qq * 2;
                unsigned bh[2], bl[2];
                bh[0] = *(const unsigned*)(Bh + cbp);
                bh[1] = *(const unsigned*)(Bh + cbp + 8);
                bl[0] = *(const unsigned*)(Bl + cbp);
                bl[1] = *(const unsigned*)(Bl + cbp + 8);
                mma_bf16(acc[0][j], ah[0], bh);
                mma_bf16(acc[1][j], ah[1], bh);
                mma_bf16(acc[0][j], al[0], bh);
                mma_bf16(acc[1][j], al[1], bh);
                mma_bf16(acc[0][j], ah[0], bl);
                mma_bf16(acc[1][j], ah[1], bl);
            }
        }
    }

    #pragma unroll
    for (int m = 0; m < 2; m++) {
        int r = row0 + warpM + m * 16 + gq;
        #pragma unroll
        for (int j = 0; j < 8; j++) {
            int cc = warpN + j * 8 + qq * 2;
            if (r < n)
                *(float2*)(outp + (size_t)r * CCH + cc) =
                    make_float2(acc[m][j][0], acc[m][j][1]);
            if (r + 8 < n)
                *(float2*)(outp + (size_t)(r + 8) * CCH + cc) =
                    make_float2(acc[m][j][2], acc[m][j][3]);
        }
    }
}

// ---------------- edge attention + aggregation -> g_agg ----------------------
// Two warps per node (4-aligned split), next-batch index prefetch.
// Writes agg/(den+eps) only; h-update + BN stats moved to k_hstats so this
// kernel depends only on g_y (gemm pass 0) + bucket.
__device__ __forceinline__ float sigf(float v) {
    return __fdividef(1.0f, 1.0f + __expf(-v));
}

__global__ void __launch_bounds__(256, 5)
k_edge(const float* __restrict__ edge_attr, int n) {
    __shared__ float4 sAgg[8][32];
    __shared__ float4 sDen[8][32];

    int wid  = threadIdx.x >> 5;
    int lane = threadIdx.x & 31;
    int node = blockIdx.x * 4 + (wid >> 1);
    int half = wid & 1;
    int cb   = lane * 4;

    float4 agg = make_float4(0.f, 0.f, 0.f, 0.f);
    float4 den = make_float4(0.f, 0.f, 0.f, 0.f);

    if (node < n) {
        int deg = g_cnt[node];
        if (deg > SLOTS) deg = SLOTS;
        int mid = ((deg >> 1) + 3) & ~3;          // 4-aligned split point
        if (mid > deg) mid = deg;
        int p0 = half ? mid : 0;
        int p1 = half ? deg : mid;
        const int* sp  = g_slot + (size_t)node * SLOTS;
        const int* srp = g_src  + (size_t)node * SLOTS;

        int p = p0;
        if (p + 4 <= p1) {
            int4 es = *(const int4*)(sp + p);
            int4 ss = *(const int4*)(srp + p);
            for (; p + 4 <= p1; ) {
                int pn = p + 4;
                int4 esn, ssn;
                if (pn + 4 <= p1) {               // prefetch next batch indices
                    esn = *(const int4*)(sp + pn);
                    ssn = *(const int4*)(srp + pn);
                }
                float4 va0 = __ldcs((const float4*)(edge_attr + (size_t)es.x * CCH + cb));
                float4 va1 = __ldcs((const float4*)(edge_attr + (size_t)es.y * CCH + cb));
                float4 va2 = __ldcs((const float4*)(edge_attr + (size_t)es.z * CCH + cb));
                float4 va3 = __ldcs((const float4*)(edge_attr + (size_t)es.w * CCH + cb));
                float4 vy0 = *(const float4*)(g_y + (size_t)ss.x * CCH + cb);
                float4 vy1 = *(const float4*)(g_y + (size_t)ss.y * CCH + cb);
                float4 vy2 = *(const float4*)(g_y + (size_t)ss.z * CCH + cb);
                float4 vy3 = *(const float4*)(g_y + (size_t)ss.w * CCH + cb);
                float g0, g1, g2, g3;
                g0 = sigf(va0.x); g1 = sigf(va1.x); g2 = sigf(va2.x); g3 = sigf(va3.x);
                den.x += (g0 + g1) + (g2 + g3);
                agg.x = fmaf(g0, vy0.x, fmaf(g1, vy1.x, fmaf(g2, vy2.x, fmaf(g3, vy3.x, agg.x))));
                g0 = sigf(va0.y); g1 = sigf(va1.y); g2 = sigf(va2.y); g3 = sigf(va3.y);
                den.y += (g0 + g1) + (g2 + g3);
                agg.y = fmaf(g0, vy0.y, fmaf(g1, vy1.y, fmaf(g2, vy2.y, fmaf(g3, vy3.y, agg.y))));
                g0 = sigf(va0.z); g1 = sigf(va1.z); g2 = sigf(va2.z); g3 = sigf(va3.z);
                den.z += (g0 + g1) + (g2 + g3);
                agg.z = fmaf(g0, vy0.z, fmaf(g1, vy1.z, fmaf(g2, vy2.z, fmaf(g3, vy3.z, agg.z))));
                g0 = sigf(va0.w); g1 = sigf(va1.w); g2 = sigf(va2.w); g3 = sigf(va3.w);
                den.w += (g0 + g1) + (g2 + g3);
                agg.w = fmaf(g0, vy0.w, fmaf(g1, vy1.w, fmaf(g2, vy2.w, fmaf(g3, vy3.w, agg.w))));
                p = pn;
                es = esn;
                ss = ssn;
            }
        }
        for (; p < p1; p++) {
            int e0 = sp[p], s0 = srp[p];
            float4 va = __ldcs((const float4*)(edge_attr + (size_t)e0 * CCH + cb));
            float4 vy = *(const float4*)(g_y + (size_t)s0 * CCH + cb);
            float gx = sigf(va.x), gy = sigf(va.y), gz = sigf(va.z), gw = sigf(va.w);
            den.x += gx;  den.y += gy;  den.z += gz;  den.w += gw;
            agg.x = fmaf(gx, vy.x, agg.x);
            agg.y = fmaf(gy, vy.y, agg.y);
            agg.z = fmaf(gz, vy.z, agg.z);
            agg.w = fmaf(gw, vy.w, agg.w);
        }
    }

    sAgg[wid][lane] = agg;
    sDen[wid][lane] = den;
    __syncthreads();

    if (node < n && half == 0) {
        float4 a2 = sAgg[wid + 1][lane];
        float4 d2 = sDen[wid + 1][lane];
        agg.x += a2.x;  agg.y += a2.y;  agg.z += a2.z;  agg.w += a2.w;
        den.x += d2.x;  den.y += d2.y;  den.z += d2.z;  den.w += d2.w;

        float4 o;
        o.x = agg.x / (den.x + 1e-8f);
        o.y = agg.y / (den.y + 1e-8f);
        o.z = agg.z / (den.z + 1e-8f);
        o.w = agg.w / (den.w + 1e-8f);
        *(float4*)(g_agg + (size_t)node * CCH + cb) = o;
    }
}

// ---------------- h = lin + agg; BN partial stats ----------------------------
__global__ void __launch_bounds__(256)
k_hstats(int n) {
    __shared__ float s_sum[CCH];
    __shared__ float s_sq[CCH];
    for (int i = threadIdx.x; i < CCH; i += 256) { s_sum[i] = 0.f; s_sq[i] = 0.f; }
    __syncthreads();

    int idx = blockIdx.x * blockDim.x + threadIdx.x;
    int total = n * (CCH / 4);
    if (idx < total) {
        int cb = (idx & (CCH / 4 - 1)) * 4;
        float4 hv = ((const float4*)g_h)[idx];
        float4 av = ((const float4*)g_agg)[idx];
        float4 h = make_float4(hv.x + av.x, hv.y + av.y, hv.z + av.z, hv.w + av.w);
        ((float4*)g_h)[idx] = h;
        atomicAdd(&s_sum[cb + 0], h.x);  atomicAdd(&s_sq[cb + 0], h.x * h.x);
        atomicAdd(&s_sum[cb + 1], h.y);  atomicAdd(&s_sq[cb + 1], h.y * h.y);
        atomicAdd(&s_sum[cb + 2], h.z);  atomicAdd(&s_sq[cb + 2], h.z * h.z);
        atomicAdd(&s_sum[cb + 3], h.w);  atomicAdd(&s_sq[cb + 3], h.w * h.w);
    }
    __syncthreads();
    if (threadIdx.x < CCH) {
        atomicAdd(&g_sum[threadIdx.x],   s_sum[threadIdx.x]);
        atomicAdd(&g_sumsq[threadIdx.x], s_sq[threadIdx.x]);
    }
}

// ---------------- epilogue with fused BN finalize ----------------
__global__ void k_out(const float* __restrict__ x,
                      const float* __restrict__ gamma,
                      const float* __restrict__ beta,
                      float* __restrict__ out, int n) {
    __shared__ float ss[CCH], sh[CCH];
    if (threadIdx.x < CCH) {
        int c = threadIdx.x;
        float invn = 1.0f / (float)n;
        float mean = g_sum[c] * invn;
        float var  = g_sumsq[c] * invn - mean * mean;
        float istd = rsqrtf(var + 1e-5f);
        float sc = istd * gamma[c];
        ss[c] = sc;
        sh[c] = beta[c] - mean * sc;
    }
    __syncthreads();
    int idx = blockIdx.x * blockDim.x + threadIdx.x;
    int total = n * (CCH / 4);
    if (idx < total) {
        int cb = (idx & (CCH / 4 - 1)) * 4;
        float4 xv = ((const float4*)x)[idx];
        float4 hv = ((const float4*)g_h)[idx];
        float4 o;
        o.x = xv.x + fmaxf(fmaf(hv.x, ss[cb + 0], sh[cb + 0]), 0.f);
        o.y = xv.y + fmaxf(fmaf(hv.y, ss[cb + 1], sh[cb + 1]), 0.f);
        o.z = xv.z + fmaxf(fmaf(hv.z, ss[cb + 2], sh[cb + 2]), 0.f);
        o.w = xv.w + fmaxf(fmaf(hv.w, ss[cb + 3], sh[cb + 3]), 0.f);
        ((float4*)out)[idx] = o;
    }
}

// ---------------- launch ----------------
extern "C" void kernel_launch(void* const* d_in, const int* in_sizes, int n_in,
                              void* d_out, int out_size) {
    const float* x     = (const float*)d_in[0];
    const float* ea    = (const float*)d_in[1];
    const int*   ei    = (const int*)d_in[2];
    const float* Wg    = (const float*)d_in[3];
    const float* Wl    = (const float*)d_in[4];
    const float* gamma = (const float*)d_in[5];
    const float* beta  = (const float*)d_in[6];
    float* out = (float*)d_out;

    int n  = in_sizes[0] / CCH;
    int nE = in_sizes[2] / 2;
    int nb = (n + 127) / 128;

    static cudaStream_t s2 = nullptr;
    static cudaEvent_t ev0 = nullptr, ev1 = nullptr, ev2 = nullptr;
    if (s2 == nullptr) {
        cudaStreamCreate(&s2);
        cudaEventCreateWithFlags(&ev0, cudaEventDisableTiming);
        cudaEventCreateWithFlags(&ev1, cudaEventDisableTiming);
        cudaEventCreateWithFlags(&ev2, cudaEventDisableTiming);
    }

    // fork: bucket + gemm_h on s2; gemm_y on main
    cudaEventRecord(ev0, 0);
    cudaStreamWaitEvent(s2, ev0, 0);

    k_zero<<<(n + 255) / 256, 256, 0, s2>>>(n);
    k_bucket<<<(nE + 255) / 256, 256, 0, s2>>>(ei, nE, n);
    cudaEventRecord(ev1, s2);                  // bucket done (k_edge needs this)
    k_gemm<<<nb, 256, 0, s2>>>(x, Wl, n, 1);   // h = x@Wl^T (under k_edge)
    cudaEventRecord(ev2, s2);                  // gemm_h done (k_hstats needs this)

    k_gemm<<<nb, 256>>>(x, Wg, n, 0);          // y = x@Wg^T on main

    cudaStreamWaitEvent(0, ev1, 0);
    k_edge<<<(n + 3) / 4, 256>>>(ea, n);       // needs y + bucket only

    cudaStreamWaitEvent(0, ev2, 0);
    k_hstats<<<(n * (CCH / 4) + 255) / 256, 256>>>(n);
    k_out<<<(n * (CCH / 4) + 255) / 256, 256>>>(x, gamma, beta, out, n);
}